// round 2
// baseline (speedup 1.0000x reference)
#include <cuda_runtime.h>

#define N_NODES 4096
#define FEA     512
#define N_EDGES 65536
#define GW      128

// Scratch (no allocs allowed): per-node gate projections + per-node edge counts
__device__ __align__(16) float g_Pt[N_NODES * GW];
__device__ __align__(16) float g_Ps[N_NODES * GW];
__device__ int g_cnt[N_NODES];

// ---------------------------------------------------------------------------
// K0: zero the output accumulator and the counts
// ---------------------------------------------------------------------------
__global__ void zero_kernel(float4* __restrict__ out4) {
    int i = blockIdx.x * 256 + threadIdx.x;
    if (i < N_NODES * FEA / 4) out4[i] = make_float4(0.f, 0.f, 0.f, 0.f);
    if (i < N_NODES) g_cnt[i] = 0;
}

// ---------------------------------------------------------------------------
// K1: per-node projections.
//   blockIdx.y == 0 : Pt[n,g] = sum_k W[g, k      ] * relu(TF[n,k])
//   blockIdx.y == 1 : Ps[n,g] = sum_k W[g, 512 + k] * relu(SF[n,k])
// Tile: 32 nodes x 128 gates, k in chunks of 32. 256 threads,
// each thread owns 4 nodes (nt*4+j) x 4 gates (gt + 32*i) = 16 accumulators.
// ---------------------------------------------------------------------------
__global__ __launch_bounds__(256) void gemm_kernel(
    const float* __restrict__ tf, const float* __restrict__ sf,
    const float* __restrict__ w) {
    __shared__ float Wsf[GW][33];   // [gate][kk]  (pad 33: bank = (g+kk)%32)
    __shared__ float Asf[32][33];   // [kk][node]

    const int t     = threadIdx.x;
    const int gt    = t & 31;       // gate lane: gates gt + 32*i
    const int nt    = t >> 5;       // node group: nodes nt*4 + j
    const int node0 = blockIdx.x * 32;

    const float* feat = blockIdx.y ? sf : tf;
    const int    wofs = blockIdx.y ? FEA : 0;
    float*       P    = blockIdx.y ? g_Ps : g_Pt;

    float acc[4][4];
    #pragma unroll
    for (int j = 0; j < 4; j++)
        #pragma unroll
        for (int i = 0; i < 4; i++) acc[j][i] = 0.f;

    for (int k0 = 0; k0 < FEA; k0 += 32) {
        // Load W tile: 128 gates x 32 k, vectorized, conflict-free stores
        #pragma unroll
        for (int r = 0; r < 4; r++) {
            int e4 = t + 256 * r;           // 0..1023
            int g  = e4 >> 3;
            int kq = e4 & 7;
            float4 wv = reinterpret_cast<const float4*>(w + g * (2 * FEA) + wofs + k0)[kq];
            Wsf[g][kq * 4 + 0] = wv.x;
            Wsf[g][kq * 4 + 1] = wv.y;
            Wsf[g][kq * 4 + 2] = wv.z;
            Wsf[g][kq * 4 + 3] = wv.w;
        }
        // Load A tile: 32 nodes x 32 k with relu, transposed into [kk][node]
        {
            int nn = t >> 3;
            int kq = t & 7;
            float4 av = reinterpret_cast<const float4*>(feat + (node0 + nn) * FEA + k0)[kq];
            Asf[kq * 4 + 0][nn] = fmaxf(av.x, 0.f);
            Asf[kq * 4 + 1][nn] = fmaxf(av.y, 0.f);
            Asf[kq * 4 + 2][nn] = fmaxf(av.z, 0.f);
            Asf[kq * 4 + 3][nn] = fmaxf(av.w, 0.f);
        }
        __syncthreads();

        #pragma unroll 8
        for (int kk = 0; kk < 32; kk++) {
            float a[4], wv[4];
            #pragma unroll
            for (int j = 0; j < 4; j++) a[j] = Asf[kk][nt * 4 + j];     // warp-broadcast
            #pragma unroll
            for (int i = 0; i < 4; i++) wv[i] = Wsf[gt + 32 * i][kk];   // conflict-free
            #pragma unroll
            for (int j = 0; j < 4; j++)
                #pragma unroll
                for (int i = 0; i < 4; i++) acc[j][i] = fmaf(a[j], wv[i], acc[j][i]);
        }
        __syncthreads();
    }

    #pragma unroll
    for (int j = 0; j < 4; j++) {
        int n = node0 + nt * 4 + j;
        #pragma unroll
        for (int i = 0; i < 4; i++)
            P[n * GW + gt + 32 * i] = acc[j][i];   // coalesced per i
    }
}

// ---------------------------------------------------------------------------
// K2: one warp per edge: gate = mean(sigmoid(Pt[ti]+Ps[si]+b)), then
// vector-RED src_f[si]*gate into out[ti], count++ on ti.
// ---------------------------------------------------------------------------
__device__ __forceinline__ float fast_sigmoid(float x) {
    return __fdividef(1.f, 1.f + __expf(-x));
}

__device__ __forceinline__ void red_add_f32x4(float4* p, float4 v) {
    asm volatile("red.global.add.v4.f32 [%0], {%1, %2, %3, %4};"
                 :: "l"(p), "f"(v.x), "f"(v.y), "f"(v.z), "f"(v.w) : "memory");
}

__global__ __launch_bounds__(256) void edge_kernel(
    const float* __restrict__ sf, const float* __restrict__ b,
    const int* __restrict__ ti, const int* __restrict__ si,
    float* __restrict__ out) {
    const int e = blockIdx.x * 8 + (threadIdx.x >> 5);
    const int lane = threadIdx.x & 31;
    if (e >= N_EDGES) return;

    const int tn = ti[e];
    const int sn = si[e];

    float4 pt = reinterpret_cast<const float4*>(g_Pt)[tn * 32 + lane];
    float4 ps = reinterpret_cast<const float4*>(g_Ps)[sn * 32 + lane];
    float4 bb = reinterpret_cast<const float4*>(b)[lane];

    float s = fast_sigmoid(pt.x + ps.x + bb.x)
            + fast_sigmoid(pt.y + ps.y + bb.y)
            + fast_sigmoid(pt.z + ps.z + bb.z)
            + fast_sigmoid(pt.w + ps.w + bb.w);
    #pragma unroll
    for (int off = 16; off; off >>= 1) s += __shfl_xor_sync(0xFFFFFFFFu, s, off);
    const float gate = s * (1.f / (float)GW);

    if (lane == 0) atomicAdd(&g_cnt[tn], 1);

    const float4* s4 = reinterpret_cast<const float4*>(sf) + sn * (FEA / 4);
    float4*       o4 = reinterpret_cast<float4*>(out) + tn * (FEA / 4);
    #pragma unroll
    for (int j = 0; j < 4; j++) {
        float4 v = s4[lane + 32 * j];
        v.x *= gate; v.y *= gate; v.z *= gate; v.w *= gate;
        red_add_f32x4(&o4[lane + 32 * j], v);
    }
}

// ---------------------------------------------------------------------------
// K3: scatter-mean normalize (count==0 rows were zeroed; inv=0 keeps them 0)
// ---------------------------------------------------------------------------
__global__ void norm_kernel(float4* __restrict__ out4) {
    int i = blockIdx.x * 256 + threadIdx.x;
    if (i >= N_NODES * FEA / 4) return;
    int n = i >> 7;                           // /(FEA/4)
    float c = (float)g_cnt[n];
    float inv = (c > 0.f) ? __fdividef(1.f, c) : 0.f;
    float4 v = out4[i];
    v.x *= inv; v.y *= inv; v.z *= inv; v.w *= inv;
    out4[i] = v;
}

extern "C" void kernel_launch(void* const* d_in, const int* in_sizes, int n_in,
                              void* d_out, int out_size) {
    const float* tf = (const float*)d_in[0];   // target_features [4096,512]
    const float* sf = (const float*)d_in[1];   // source_features [4096,512]
    const float* w  = (const float*)d_in[2];   // [128, 1024]
    const float* b  = (const float*)d_in[3];   // [128]
    const int*   ti = (const int*)d_in[4];     // [65536]
    const int*   si = (const int*)d_in[5];     // [65536]
    float*       out = (float*)d_out;          // [4096,512]

    zero_kernel<<<(N_NODES * FEA / 4 + 255) / 256, 256>>>((float4*)out);

    dim3 gg(N_NODES / 32, 2);
    gemm_kernel<<<gg, 256>>>(tf, sf, w);

    edge_kernel<<<N_EDGES / 8, 256>>>(sf, b, ti, si, out);

    norm_kernel<<<(N_NODES * FEA / 4 + 255) / 256, 256>>>((float4*)out);
}

// round 3
// speedup vs baseline: 1.0063x; 1.0063x over previous
#include <cuda_runtime.h>

#define N_NODES 4096
#define FEA     512
#define N_EDGES 65536
#define GW      128

// Scratch (no allocs allowed)
__device__ __align__(16) float g_Pt[N_NODES * GW];
__device__ __align__(16) float g_Ps[N_NODES * GW];
__device__ float g_gate[N_EDGES];
__device__ int2  g_bucket[N_EDGES];     // {source_node, gate_bits} per edge, CSR order
__device__ int   g_cnt[N_NODES];
__device__ int   g_rowstart[N_NODES];
__device__ int   g_cursor[N_NODES];

// ---------------------------------------------------------------------------
// K0: zero per-node counts
// ---------------------------------------------------------------------------
__global__ void zero_cnt_kernel() {
    int i = blockIdx.x * 256 + threadIdx.x;
    if (i < N_NODES) g_cnt[i] = 0;
}

// ---------------------------------------------------------------------------
// K1: count incoming edges per target node
// ---------------------------------------------------------------------------
__global__ __launch_bounds__(256) void count_kernel(const int* __restrict__ ti) {
    int e = blockIdx.x * 256 + threadIdx.x;
    atomicAdd(&g_cnt[ti[e]], 1);
}

// ---------------------------------------------------------------------------
// K2: exclusive prefix sum over the 4096 counts (single block, 1024 threads,
// 4 counts/thread; Hillis-Steele over per-thread partials)
// ---------------------------------------------------------------------------
__global__ __launch_bounds__(1024) void scan_kernel() {
    __shared__ int sm[1024];
    int t = threadIdx.x;
    int base = t * 4;
    int c[4], s = 0;
    #pragma unroll
    for (int j = 0; j < 4; j++) { c[j] = g_cnt[base + j]; s += c[j]; }
    sm[t] = s;
    __syncthreads();
    for (int off = 1; off < 1024; off <<= 1) {
        int v = (t >= off) ? sm[t - off] : 0;
        __syncthreads();
        sm[t] += v;
        __syncthreads();
    }
    int excl = (t > 0) ? sm[t - 1] : 0;
    #pragma unroll
    for (int j = 0; j < 4; j++) {
        g_rowstart[base + j] = excl;
        g_cursor[base + j]   = excl;
        excl += c[j];
    }
}

// ---------------------------------------------------------------------------
// K3: per-node gate projections with packed f32x2 FMA.
//   blockIdx.y == 0 : Pt[n,g] = sum_k W[g, k      ] * relu(TF[n,k])
//   blockIdx.y == 1 : Ps[n,g] = sum_k W[g, 512 + k] * relu(SF[n,k])
// Tile 32 nodes x 128 gates, k chunks of 32. Thread (gt,nt) owns nodes
// nt*4..nt*4+3 and gate PAIRS (2gt,2gt+1) and (64+2gt,64+2gt+1).
// Wsf is [kk][gate] (stride 130 floats: LDS.64 gate-pair reads conflict-free),
// Asf is [kk][node] (stride 36: one broadcast LDS.128 per kk).
// ---------------------------------------------------------------------------
#define FMA2(acc, a, b) \
    asm("fma.rn.f32x2 %0, %1, %2, %0;" : "+l"(acc) : "l"(a), "l"(b))
#define PACKDUP(d, x) \
    asm("mov.b64 %0, {%1, %1};" : "=l"(d) : "f"(x))

__global__ __launch_bounds__(256) void gemm_kernel(
    const float* __restrict__ tf, const float* __restrict__ sf,
    const float* __restrict__ w) {
    __shared__ __align__(16) float Wsf[32][130];  // [kk][gate]
    __shared__ __align__(16) float Asf[32][36];   // [kk][node]

    const int t     = threadIdx.x;
    const int gt    = t & 31;
    const int nt    = t >> 5;
    const int node0 = blockIdx.x * 32;

    const float* feat = blockIdx.y ? sf : tf;
    const int    wofs = blockIdx.y ? FEA : 0;
    float*       P    = blockIdx.y ? g_Ps : g_Pt;

    unsigned long long acc[4][2];
    #pragma unroll
    for (int j = 0; j < 4; j++) { acc[j][0] = 0ull; acc[j][1] = 0ull; }

    for (int k0 = 0; k0 < FEA; k0 += 32) {
        // W tile: 128 gates x 32 k, transposed into [kk][gate]
        #pragma unroll
        for (int r = 0; r < 4; r++) {
            int e4 = t + 256 * r;          // 0..1023
            int g  = e4 >> 3;
            int kq = e4 & 7;
            float4 wv = reinterpret_cast<const float4*>(w + g * (2 * FEA) + wofs + k0)[kq];
            Wsf[kq * 4 + 0][g] = wv.x;
            Wsf[kq * 4 + 1][g] = wv.y;
            Wsf[kq * 4 + 2][g] = wv.z;
            Wsf[kq * 4 + 3][g] = wv.w;
        }
        // A tile: 32 nodes x 32 k with relu, transposed into [kk][node]
        {
            int nn = t >> 3;
            int kq = t & 7;
            float4 av = reinterpret_cast<const float4*>(feat + (node0 + nn) * FEA + k0)[kq];
            Asf[kq * 4 + 0][nn] = fmaxf(av.x, 0.f);
            Asf[kq * 4 + 1][nn] = fmaxf(av.y, 0.f);
            Asf[kq * 4 + 2][nn] = fmaxf(av.z, 0.f);
            Asf[kq * 4 + 3][nn] = fmaxf(av.w, 0.f);
        }
        __syncthreads();

        #pragma unroll 8
        for (int kk = 0; kk < 32; kk++) {
            float4 a4 = *reinterpret_cast<const float4*>(&Asf[kk][nt * 4]);     // broadcast
            unsigned long long w20 = *reinterpret_cast<const unsigned long long*>(&Wsf[kk][2 * gt]);
            unsigned long long w21 = *reinterpret_cast<const unsigned long long*>(&Wsf[kk][64 + 2 * gt]);
            unsigned long long ad[4];
            PACKDUP(ad[0], a4.x);
            PACKDUP(ad[1], a4.y);
            PACKDUP(ad[2], a4.z);
            PACKDUP(ad[3], a4.w);
            #pragma unroll
            for (int j = 0; j < 4; j++) {
                FMA2(acc[j][0], ad[j], w20);
                FMA2(acc[j][1], ad[j], w21);
            }
        }
        __syncthreads();
    }

    #pragma unroll
    for (int j = 0; j < 4; j++) {
        int n = node0 + nt * 4 + j;
        *reinterpret_cast<unsigned long long*>(&P[n * GW + 2 * gt])      = acc[j][0];
        *reinterpret_cast<unsigned long long*>(&P[n * GW + 64 + 2 * gt]) = acc[j][1];
    }
}

// ---------------------------------------------------------------------------
// K4: one warp per edge: gate[e] = mean(sigmoid(Pt[ti]+Ps[si]+b))
// ---------------------------------------------------------------------------
__device__ __forceinline__ float fast_sigmoid(float x) {
    return __fdividef(1.f, 1.f + __expf(-x));
}

__global__ __launch_bounds__(256) void gate_kernel(
    const float* __restrict__ b,
    const int* __restrict__ ti, const int* __restrict__ si) {
    const int e = blockIdx.x * 8 + (threadIdx.x >> 5);
    const int lane = threadIdx.x & 31;

    const int tn = ti[e];
    const int sn = si[e];

    float4 pt = reinterpret_cast<const float4*>(g_Pt)[tn * 32 + lane];
    float4 ps = reinterpret_cast<const float4*>(g_Ps)[sn * 32 + lane];
    float4 bb = reinterpret_cast<const float4*>(b)[lane];

    float s = fast_sigmoid(pt.x + ps.x + bb.x)
            + fast_sigmoid(pt.y + ps.y + bb.y)
            + fast_sigmoid(pt.z + ps.z + bb.z)
            + fast_sigmoid(pt.w + ps.w + bb.w);
    #pragma unroll
    for (int off = 16; off; off >>= 1) s += __shfl_xor_sync(0xFFFFFFFFu, s, off);
    if (lane == 0) g_gate[e] = s * (1.f / (float)GW);
}

// ---------------------------------------------------------------------------
// K5: bucket edges by target node (CSR payload = {src node, gate bits})
// ---------------------------------------------------------------------------
__global__ __launch_bounds__(256) void bucket_kernel(
    const int* __restrict__ ti, const int* __restrict__ si) {
    int e = blockIdx.x * 256 + threadIdx.x;
    int tn = ti[e];
    int pos = atomicAdd(&g_cursor[tn], 1);
    g_bucket[pos] = make_int2(si[e], __float_as_int(g_gate[e]));
}

// ---------------------------------------------------------------------------
// K6: one block (128 thr) per node: gather gated src rows, write mean.
// Writes EVERY output element (deg-0 nodes get zeros) -> no zero/norm passes.
// ---------------------------------------------------------------------------
__global__ __launch_bounds__(128) void node_kernel(
    const float* __restrict__ sf, float* __restrict__ out) {
    const int n = blockIdx.x;
    const int t = threadIdx.x;
    const int beg = g_rowstart[n];
    const int cnt = g_cnt[n];

    float4 acc = make_float4(0.f, 0.f, 0.f, 0.f);
    const float4* s4 = reinterpret_cast<const float4*>(sf);

    if (cnt > 0) {
        int2 p = g_bucket[beg];
        for (int i = 0; i < cnt; i++) {
            int2 np = (i + 1 < cnt) ? g_bucket[beg + i + 1] : p;  // prefetch
            float g  = __int_as_float(p.y);
            float4 v = s4[p.x * (FEA / 4) + t];
            acc.x = fmaf(v.x, g, acc.x);
            acc.y = fmaf(v.y, g, acc.y);
            acc.z = fmaf(v.z, g, acc.z);
            acc.w = fmaf(v.w, g, acc.w);
            p = np;
        }
        float inv = __fdividef(1.f, (float)cnt);
        acc.x *= inv; acc.y *= inv; acc.z *= inv; acc.w *= inv;
    }
    reinterpret_cast<float4*>(out)[n * (FEA / 4) + t] = acc;
}

extern "C" void kernel_launch(void* const* d_in, const int* in_sizes, int n_in,
                              void* d_out, int out_size) {
    const float* tf = (const float*)d_in[0];   // target_features [4096,512]
    const float* sf = (const float*)d_in[1];   // source_features [4096,512]
    const float* w  = (const float*)d_in[2];   // [128, 1024]
    const float* b  = (const float*)d_in[3];   // [128]
    const int*   ti = (const int*)d_in[4];     // [65536]
    const int*   si = (const int*)d_in[5];     // [65536]
    float*       out = (float*)d_out;          // [4096,512]

    zero_cnt_kernel<<<N_NODES / 256, 256>>>();
    count_kernel<<<N_EDGES / 256, 256>>>(ti);
    scan_kernel<<<1, 1024>>>();

    dim3 gg(N_NODES / 32, 2);
    gemm_kernel<<<gg, 256>>>(tf, sf, w);

    gate_kernel<<<N_EDGES / 8, 256>>>(b, ti, si);
    bucket_kernel<<<N_EDGES / 256, 256>>>(ti, si);
    node_kernel<<<N_NODES, 128>>>(sf, out);
}

// round 17
// speedup vs baseline: 1.0832x; 1.0764x over previous
#include <cuda_runtime.h>

#define N_NODES 4096
#define FEA     512
#define N_EDGES 65536
#define GW      128
#define KSPLIT  4

// Scratch (no allocs allowed)
__device__ __align__(16) float g_PtP[KSPLIT][N_NODES * GW];  // k-split partials
__device__ __align__(16) float g_PsP[KSPLIT][N_NODES * GW];
__device__ __align__(16) float g_Pt[N_NODES * GW];
__device__ __align__(16) float g_Ps[N_NODES * GW];
__device__ int2  g_bucket[N_EDGES];     // {source_node, gate_bits} per edge, CSR order
__device__ int   g_cnt[N_NODES];
__device__ int   g_rowstart[N_NODES];
__device__ int   g_cursor[N_NODES];

// ---------------------------------------------------------------------------
// K0: zero per-node counts
// ---------------------------------------------------------------------------
__global__ void zero_cnt_kernel() {
    int i = blockIdx.x * 256 + threadIdx.x;
    if (i < N_NODES) g_cnt[i] = 0;
}

// ---------------------------------------------------------------------------
// K1: count incoming edges per target node
// ---------------------------------------------------------------------------
__global__ __launch_bounds__(256) void count_kernel(const int* __restrict__ ti) {
    int e = blockIdx.x * 256 + threadIdx.x;
    atomicAdd(&g_cnt[ti[e]], 1);
}

// ---------------------------------------------------------------------------
// K2: exclusive prefix sum over the 4096 counts (single block, 1024 threads)
// ---------------------------------------------------------------------------
__global__ __launch_bounds__(1024) void scan_kernel() {
    __shared__ int sm[1024];
    int t = threadIdx.x;
    int base = t * 4;
    int c[4], s = 0;
    #pragma unroll
    for (int j = 0; j < 4; j++) { c[j] = g_cnt[base + j]; s += c[j]; }
    sm[t] = s;
    __syncthreads();
    for (int off = 1; off < 1024; off <<= 1) {
        int v = (t >= off) ? sm[t - off] : 0;
        __syncthreads();
        sm[t] += v;
        __syncthreads();
    }
    int excl = (t > 0) ? sm[t - 1] : 0;
    #pragma unroll
    for (int j = 0; j < 4; j++) {
        g_rowstart[base + j] = excl;
        g_cursor[base + j]   = excl;
        excl += c[j];
    }
}

// ---------------------------------------------------------------------------
// K3: per-node gate projections, k-split 4 ways for occupancy.
//   blockIdx.y: 0 -> target side (W[:, 0:512] * relu(TF))
//               1 -> source side (W[:, 512:1024] * relu(SF))
//   blockIdx.z: k chunk (128 k-values each) -> partial array
// Tile 32 nodes x 128 gates. Thread (gt,nt) owns nodes nt*4..nt*4+3 and gate
// pairs (2gt, 2gt+1), (64+2gt, 64+2gt+1). Packed f32x2 FMA inner loop.
// ---------------------------------------------------------------------------
#define FMA2(acc, a, b) \
    asm("fma.rn.f32x2 %0, %1, %2, %0;" : "+l"(acc) : "l"(a), "l"(b))
#define PACKDUP(d, x) \
    asm("mov.b64 %0, {%1, %1};" : "=l"(d) : "f"(x))

__global__ __launch_bounds__(256) void gemm_kernel(
    const float* __restrict__ tf, const float* __restrict__ sf,
    const float* __restrict__ w) {
    __shared__ __align__(16) float Wsf[32][130];  // [kk][gate]
    __shared__ __align__(16) float Asf[32][36];   // [kk][node]

    const int t     = threadIdx.x;
    const int gt    = t & 31;
    const int nt    = t >> 5;
    const int node0 = blockIdx.x * 32;
    const int ks    = blockIdx.z;

    const float* feat = blockIdx.y ? sf : tf;
    const int    wofs = blockIdx.y ? FEA : 0;
    float*       P    = blockIdx.y ? g_PsP[ks] : g_PtP[ks];

    unsigned long long acc[4][2];
    #pragma unroll
    for (int j = 0; j < 4; j++) { acc[j][0] = 0ull; acc[j][1] = 0ull; }

    const int kbeg = ks * (FEA / KSPLIT);
    const int kend = kbeg + (FEA / KSPLIT);

    for (int k0 = kbeg; k0 < kend; k0 += 32) {
        // W tile: 128 gates x 32 k, transposed into [kk][gate]
        #pragma unroll
        for (int r = 0; r < 4; r++) {
            int e4 = t + 256 * r;          // 0..1023
            int g  = e4 >> 3;
            int kq = e4 & 7;
            float4 wv = reinterpret_cast<const float4*>(w + g * (2 * FEA) + wofs + k0)[kq];
            Wsf[kq * 4 + 0][g] = wv.x;
            Wsf[kq * 4 + 1][g] = wv.y;
            Wsf[kq * 4 + 2][g] = wv.z;
            Wsf[kq * 4 + 3][g] = wv.w;
        }
        // A tile: 32 nodes x 32 k with relu, transposed into [kk][node]
        {
            int nn = t >> 3;
            int kq = t & 7;
            float4 av = reinterpret_cast<const float4*>(feat + (node0 + nn) * FEA + k0)[kq];
            Asf[kq * 4 + 0][nn] = fmaxf(av.x, 0.f);
            Asf[kq * 4 + 1][nn] = fmaxf(av.y, 0.f);
            Asf[kq * 4 + 2][nn] = fmaxf(av.z, 0.f);
            Asf[kq * 4 + 3][nn] = fmaxf(av.w, 0.f);
        }
        __syncthreads();

        #pragma unroll 8
        for (int kk = 0; kk < 32; kk++) {
            float4 a4 = *reinterpret_cast<const float4*>(&Asf[kk][nt * 4]);     // broadcast
            unsigned long long w20 = *reinterpret_cast<const unsigned long long*>(&Wsf[kk][2 * gt]);
            unsigned long long w21 = *reinterpret_cast<const unsigned long long*>(&Wsf[kk][64 + 2 * gt]);
            unsigned long long ad[4];
            PACKDUP(ad[0], a4.x);
            PACKDUP(ad[1], a4.y);
            PACKDUP(ad[2], a4.z);
            PACKDUP(ad[3], a4.w);
            #pragma unroll
            for (int j = 0; j < 4; j++) {
                FMA2(acc[j][0], ad[j], w20);
                FMA2(acc[j][1], ad[j], w21);
            }
        }
        __syncthreads();
    }

    #pragma unroll
    for (int j = 0; j < 4; j++) {
        int n = node0 + nt * 4 + j;
        *reinterpret_cast<unsigned long long*>(&P[n * GW + 2 * gt])      = acc[j][0];
        *reinterpret_cast<unsigned long long*>(&P[n * GW + 64 + 2 * gt]) = acc[j][1];
    }
}

// ---------------------------------------------------------------------------
// K3b: reduce the 4 k-split partials into g_Pt / g_Ps (float4 streaming)
// ---------------------------------------------------------------------------
__global__ __launch_bounds__(256) void reduce_kernel() {
    int i = blockIdx.x * 256 + threadIdx.x;            // over 2 * N*GW/4
    const int per_side = N_NODES * GW / 4;
    int side = i >= per_side;
    int idx  = side ? i - per_side : i;
    const float4* p0 = reinterpret_cast<const float4*>(side ? g_PsP[0] : g_PtP[0]);
    const float4* p1 = reinterpret_cast<const float4*>(side ? g_PsP[1] : g_PtP[1]);
    const float4* p2 = reinterpret_cast<const float4*>(side ? g_PsP[2] : g_PtP[2]);
    const float4* p3 = reinterpret_cast<const float4*>(side ? g_PsP[3] : g_PtP[3]);
    float4 a = p0[idx], bb = p1[idx], c = p2[idx], d = p3[idx];
    float4 r;
    r.x = (a.x + bb.x) + (c.x + d.x);
    r.y = (a.y + bb.y) + (c.y + d.y);
    r.z = (a.z + bb.z) + (c.z + d.z);
    r.w = (a.w + bb.w) + (c.w + d.w);
    reinterpret_cast<float4*>(side ? g_Ps : g_Pt)[idx] = r;
}

// ---------------------------------------------------------------------------
// K4: one warp per edge: gate = mean(sigmoid(Pt[ti]+Ps[si]+b)), then lane 0
// claims the CSR slot (atomic cursor) and writes {src, gate} directly.
// (Fused former gate_kernel + bucket_kernel; kills g_gate + one pass.)
// ---------------------------------------------------------------------------
__device__ __forceinline__ float fast_sigmoid(float x) {
    return __fdividef(1.f, 1.f + __expf(-x));
}

__global__ __launch_bounds__(256) void gate_bucket_kernel(
    const float* __restrict__ b,
    const int* __restrict__ ti, const int* __restrict__ si) {
    const int e = blockIdx.x * 8 + (threadIdx.x >> 5);
    const int lane = threadIdx.x & 31;

    const int tn = ti[e];
    const int sn = si[e];

    float4 pt = reinterpret_cast<const float4*>(g_Pt)[tn * 32 + lane];
    float4 ps = reinterpret_cast<const float4*>(g_Ps)[sn * 32 + lane];
    float4 bb = reinterpret_cast<const float4*>(b)[lane];

    float s = fast_sigmoid(pt.x + ps.x + bb.x)
            + fast_sigmoid(pt.y + ps.y + bb.y)
            + fast_sigmoid(pt.z + ps.z + bb.z)
            + fast_sigmoid(pt.w + ps.w + bb.w);
    #pragma unroll
    for (int off = 16; off; off >>= 1) s += __shfl_xor_sync(0xFFFFFFFFu, s, off);

    if (lane == 0) {
        float gate = s * (1.f / (float)GW);
        int pos = atomicAdd(&g_cursor[tn], 1);
        g_bucket[pos] = make_int2(sn, __float_as_int(gate));
    }
}

// ---------------------------------------------------------------------------
// K5: one block (128 thr) per node: gather gated src rows, write mean.
// Writes EVERY output element (deg-0 nodes get zeros) -> no zero/norm passes.
// ---------------------------------------------------------------------------
__global__ __launch_bounds__(128) void node_kernel(
    const float* __restrict__ sf, float* __restrict__ out) {
    const int n = blockIdx.x;
    const int t = threadIdx.x;
    const int beg = g_rowstart[n];
    const int cnt = g_cnt[n];

    float4 acc = make_float4(0.f, 0.f, 0.f, 0.f);
    const float4* s4 = reinterpret_cast<const float4*>(sf);

    if (cnt > 0) {
        int2 p = g_bucket[beg];
        for (int i = 0; i < cnt; i++) {
            int2 np = (i + 1 < cnt) ? g_bucket[beg + i + 1] : p;  // prefetch
            float g  = __int_as_float(p.y);
            float4 v = s4[p.x * (FEA / 4) + t];
            acc.x = fmaf(v.x, g, acc.x);
            acc.y = fmaf(v.y, g, acc.y);
            acc.z = fmaf(v.z, g, acc.z);
            acc.w = fmaf(v.w, g, acc.w);
            p = np;
        }
        float inv = __fdividef(1.f, (float)cnt);
        acc.x *= inv; acc.y *= inv; acc.z *= inv; acc.w *= inv;
    }
    reinterpret_cast<float4*>(out)[n * (FEA / 4) + t] = acc;
}

extern "C" void kernel_launch(void* const* d_in, const int* in_sizes, int n_in,
                              void* d_out, int out_size) {
    const float* tf = (const float*)d_in[0];   // target_features [4096,512]
    const float* sf = (const float*)d_in[1];   // source_features [4096,512]
    const float* w  = (const float*)d_in[2];   // [128, 1024]
    const float* b  = (const float*)d_in[3];   // [128]
    const int*   ti = (const int*)d_in[4];     // [65536]
    const int*   si = (const int*)d_in[5];     // [65536]
    float*       out = (float*)d_out;          // [4096,512]

    zero_cnt_kernel<<<N_NODES / 256, 256>>>();
    count_kernel<<<N_EDGES / 256, 256>>>(ti);
    scan_kernel<<<1, 1024>>>();

    dim3 gg(N_NODES / 32, 2, KSPLIT);
    gemm_kernel<<<gg, 256>>>(tf, sf, w);
    reduce_kernel<<<(2 * N_NODES * GW / 4) / 256, 256>>>();

    gate_bucket_kernel<<<N_EDGES / 8, 256>>>(b, ti, si);
    node_kernel<<<N_NODES, 128>>>(sf, out);
}